// round 12
// baseline (speedup 1.0000x reference)
#include <cuda_runtime.h>
#include <cuda_fp16.h>
#include <cstdint>
#include <math.h>

// ============================================================================
// conv1 via mma.sync fp16 (HMMA), pure fp16 inputs. K' = 4608 (9 taps * 512).
// Storage: padded 26x26 planes (zeros at borders) so tap shifts are linear.
// R12: prop stages all 32 channels once (1 barrier/block); conv1 issues
// cp.async after first MMA burst; snprep merged into wprep.
// CTA 128Mx256N, 512 thr, warp 32x64, K-chunk 64, 4-stage cp.async.
// ============================================================================

#define NPLANE   676
#define KPRIME   512               // per-tap k' (pure fp16)
#define N_CHUNKS 72                // 9 taps * 8 chunks of 64
#define STAGE_B  49152             // A 16KB + B 32KB
#define N_STAGE  4
#define CONV1_SMEM (N_STAGE * STAGE_B)   // 196608B; epilogue reuses this arena

// epilogue smem layout (floats):
#define XS_STRIDE 292
#define W2S_OFF   37376
#define B2S_OFF   44544

// ---------------- static device scratch ----------------
__device__ __half g_xs[130 * NPLANE * KPRIME];   // padded NHWC fp16 (~90MB)
__device__ __half g_wb[9 * 256 * KPRIME];        // weights [tap][n][k]
__device__ float g_scale[256];
__device__ float g_shift[256];
__device__ float g_kmap[128 * 25 * 576];         // softmax maps

// ---------------- PTX helpers ----------------
__device__ __forceinline__ uint32_t smem_u32(const void* p) {
    uint32_t a;
    asm("{ .reg .u64 t; cvta.to.shared.u64 t, %1; cvt.u32.u64 %0, t; }" : "=r"(a) : "l"(p));
    return a;
}
#define CP_ASYNC16(dst, src) \
    asm volatile("cp.async.cg.shared.global [%0], [%1], 16;" :: "r"(dst), "l"(src) : "memory")
#define CP_COMMIT() asm volatile("cp.async.commit_group;" ::: "memory")
#define CP_WAIT(n)  asm volatile("cp.async.wait_group %0;" :: "n"(n) : "memory")

__device__ __forceinline__ void ldsm_x4(uint32_t* r, uint32_t addr) {
    asm volatile("ldmatrix.sync.aligned.m8n8.x4.shared.b16 {%0,%1,%2,%3}, [%4];"
                 : "=r"(r[0]), "=r"(r[1]), "=r"(r[2]), "=r"(r[3]) : "r"(addr));
}
__device__ __forceinline__ void mma_f16(float* c, const uint32_t* a, uint32_t b0, uint32_t b1) {
    asm volatile("mma.sync.aligned.m16n8k16.row.col.f32.f16.f16.f32 "
                 "{%0,%1,%2,%3}, {%4,%5,%6,%7}, {%8,%9}, {%0,%1,%2,%3};"
                 : "+f"(c[0]), "+f"(c[1]), "+f"(c[2]), "+f"(c[3])
                 : "r"(a[0]), "r"(a[1]), "r"(a[2]), "r"(a[3]), "r"(b0), "r"(b1));
}

// ---------------- prep: weights -> fp16 [tap][n][k]  (+ BN fold in block 0) --
__global__ void wprep_kernel(const float* __restrict__ w1,
                             const float* __restrict__ b1, const float* __restrict__ gam,
                             const float* __restrict__ bet, const float* __restrict__ mu,
                             const float* __restrict__ var) {
    int idx = blockIdx.x * 256 + threadIdx.x;
    if (blockIdx.x == 0) {
        int i = threadIdx.x;
        float inv = gam[i] * rsqrtf(var[i] + 1e-5f);
        g_scale[i] = inv;
        g_shift[i] = bet[i] + (b1[i] - mu[i]) * inv;
    }
    if (idx >= 9 * 256 * KPRIME) return;
    int kp = idx & 511;
    int n = (idx >> 9) & 255;
    int tap = idx >> 17;
    g_wb[idx] = __float2half(w1[((size_t)n * 512 + kp) * 9 + tap]);
}

// ---------------- prep: inputs -> padded NHWC fp16 (planes 1..128 only) -----
__global__ __launch_bounds__(256) void xprep_kernel(const float* __restrict__ src,
                                                    const float* __restrict__ det) {
    __shared__ float s[256][25];
    int blk = blockIdx.x;
    int p = blk / 26 + 1;          // planes 1..128 (guards never read)
    int yq = blk % 26;
    int t = threadIdx.x;
    __half* rowout = g_xs + (size_t)(p * NPLANE + yq * 26) * KPRIME;
    if (yq < 1 || yq > 24) {       // pad rows
        uint4 z = make_uint4(0, 0, 0, 0);
        uint4* o = (uint4*)rowout;
        for (int e = t; e < 26 * KPRIME / 8; e += 256) o[e] = z;
        return;
    }
    int b = p - 1, y = yq - 1;
    {
        uint4 z = make_uint4(0, 0, 0, 0);
        uint4* o0 = (uint4*)rowout;
        uint4* o1 = (uint4*)(rowout + (size_t)25 * KPRIME);
        for (int e = t; e < KPRIME / 8; e += 256) { o0[e] = z; o1[e] = z; }
    }
    for (int pass = 0; pass < 2; ++pass) {
        const float* in = pass ? det : src;
        for (int e = t; e < 256 * 24; e += 256) {
            int ch = e / 24, x = e - ch * 24;
            s[ch][x] = in[((size_t)b * 256 + ch) * 576 + y * 24 + x];
        }
        __syncthreads();
        int cb = pass * 256;
        for (int x = 0; x < 24; ++x) {
            __half* o = rowout + (size_t)(x + 1) * KPRIME;
            o[cb + t] = __float2half(s[t][x]);
        }
        __syncthreads();
    }
}

// ---------------- conv1 + conv2 + softmax fused ----------------
__global__ __launch_bounds__(512) void conv1_mma(const float* __restrict__ w2,
                                                 const float* __restrict__ b2) {
    extern __shared__ __align__(1024) char smem_raw[];
    const uint32_t sbase = smem_u32(smem_raw);

    const int t = threadIdx.x;
    const int l = t & 31;
    const int w = t >> 5;                   // 0..15
    const int m0 = blockIdx.x * 128;

    // ---- A staging: row = t>>2 (interior m), quarter q=t&3, 2x16B ----
    const int arow = t >> 2;
    const int aq = t & 3;
    uint32_t sdstA[2];
#pragma unroll
    for (int g = 0; g < 2; g++) {
        int ch = aq * 2 + g;
        sdstA[g] = (uint32_t)arow * 128u + (uint32_t)((ch ^ (arow & 7)) * 16);
    }
    size_t abase;
    {
        const int mg = m0 + arow;
        const int b = mg / 576;
        const int pos = mg - b * 576;
        const int yy = pos / 24;
        const int xx = pos - yy * 24;
        abase = ((size_t)(b + 1) * NPLANE + (yy + 1) * 26 + (xx + 1)) * KPRIME
              + (size_t)aq * 16;
    }
    const int brow = t >> 1;
    const int bh = t & 1;
    uint32_t sdstB[4];
#pragma unroll
    for (int g = 0; g < 4; g++) {
        int ch = bh * 4 + g;
        sdstB[g] = 16384u + (uint32_t)brow * 128u + (uint32_t)((ch ^ (brow & 7)) * 16);
    }

    // ---- compute-side precompute ----
    const int wm = (w >> 2) * 32;            // warp M (0/32/64/96)
    const int wn = (w & 3) * 64;             // warp N (0/64/128/192)
    const uint32_t rsw = (uint32_t)(l & 7);
    const uint32_t kHi = (uint32_t)(l >> 4);
    uint32_t aRow[2], bRow[4];
#pragma unroll
    for (int mi = 0; mi < 2; mi++) aRow[mi] = (uint32_t)(wm + mi * 16 + (l & 15)) * 128u;
#pragma unroll
    for (int gi = 0; gi < 4; gi++) bRow[gi] = 16384u + (uint32_t)(wn + gi * 16 + (l & 15)) * 128u;

    float acc[2][8][4];
#pragma unroll
    for (int mi = 0; mi < 2; mi++)
#pragma unroll
        for (int ni = 0; ni < 8; ni++)
#pragma unroll
            for (int r = 0; r < 4; r++) acc[mi][ni][r] = 0.f;

    auto issue = [&](int c) {
        const int tap = c >> 3;
        const int kc = (c & 7) * 64;
        const int ty = tap / 3, tx = tap - ty * 3;
        const int shift = (ty - 1) * 26 + (tx - 1);
        const uint32_t St = sbase + (uint32_t)(c & (N_STAGE - 1)) * STAGE_B;
        const __half* asrc = g_xs + abase + (ptrdiff_t)shift * KPRIME + kc;
        const __half* bsrc = g_wb + ((size_t)(tap * 256 + brow)) * KPRIME + kc + bh * 32;
#pragma unroll
        for (int g = 0; g < 2; g++) CP_ASYNC16(St + sdstA[g], asrc + g * 8);
#pragma unroll
        for (int g = 0; g < 4; g++) CP_ASYNC16(St + sdstB[g], bsrc + g * 8);
    };

    uint32_t af[2][2][4], bf[2][4][4];
    auto load_frag = [&](uint32_t St, int ks, int buf) {
        const uint32_t off = (((uint32_t)(ks * 2) + kHi) ^ rsw) << 4;
#pragma unroll
        for (int mi = 0; mi < 2; mi++) ldsm_x4(af[buf][mi], St + aRow[mi] + off);
#pragma unroll
        for (int gi = 0; gi < 4; gi++) ldsm_x4(bf[buf][gi], St + bRow[gi] + off);
    };
    auto mma_frag = [&](int buf) {
#pragma unroll
        for (int mi = 0; mi < 2; mi++)
#pragma unroll
            for (int gi = 0; gi < 4; gi++) {
                mma_f16(acc[mi][gi * 2 + 0], af[buf][mi], bf[buf][gi][0], bf[buf][gi][2]);
                mma_f16(acc[mi][gi * 2 + 1], af[buf][mi], bf[buf][gi][1], bf[buf][gi][3]);
            }
    };

    issue(0); CP_COMMIT();
    issue(1); CP_COMMIT();
    issue(2); CP_COMMIT();
    for (int c = 0; c < N_CHUNKS; ++c) {
        // chunks c AND c+1 ready before barrier (c+1 ks0 frags rolled this iter)
        if (c < N_CHUNKS - 2) { CP_WAIT(1); } else { CP_WAIT(0); }
        __syncthreads();
        const uint32_t St  = sbase + (uint32_t)(c & (N_STAGE - 1)) * STAGE_B;
        const uint32_t Stn = sbase + (uint32_t)((c + 1) & (N_STAGE - 1)) * STAGE_B;
        if (c == 0) load_frag(St, 0, 0);     // prime once
        // ks=0: MMAs first (frags rolled/primed), THEN the cp.async burst
        load_frag(St, 1, 1);
        mma_frag(0);
        if (c + 3 < N_CHUNKS) { issue(c + 3); CP_COMMIT(); }
        // ks=1
        load_frag(St, 2, 0);
        mma_frag(1);
        // ks=2
        load_frag(St, 3, 1);
        mma_frag(0);
        // ks=3 (+ roll into next chunk)
        if (c + 1 < N_CHUNKS) load_frag(Stn, 0, 0);
        mma_frag(1);
    }

    // ================== fused epilogue: BN+ReLU -> conv2 -> softmax ==========
    __syncthreads();                          // all ldsm done; arena reusable
    float* smf = (float*)smem_raw;
    float* xs  = smf;                         // [128][292]
    float* w2s = smf + W2S_OFF;               // [256][28]  (transposed w2)
    float* b2s = smf + B2S_OFF;               // [25]

    for (int e = t; e < 25 * 256; e += 512) {
        int n = e >> 8, ch = e & 255;
        w2s[ch * 28 + n] = w2[n * 256 + ch];
    }
    if (t < 25) b2s[t] = b2[t];

    // BN + ReLU, stage x1 into xs
#pragma unroll
    for (int ni = 0; ni < 8; ni++) {
        int n0 = wn + (ni >> 1) * 16 + (ni & 1) * 8 + (l & 3) * 2;
        float sc0 = g_scale[n0], sh0 = g_shift[n0];
        float sc1 = g_scale[n0 + 1], sh1 = g_shift[n0 + 1];
#pragma unroll
        for (int mi = 0; mi < 2; mi++)
#pragma unroll
            for (int h = 0; h < 2; h++) {
                int ml = wm + mi * 16 + (l >> 2) + h * 8;
                float v0 = fmaxf(fmaf(acc[mi][ni][h * 2 + 0], sc0, sh0), 0.f);
                float v1 = fmaxf(fmaf(acc[mi][ni][h * 2 + 1], sc1, sh1), 0.f);
                xs[ml * XS_STRIDE + n0] = v0;
                xs[ml * XS_STRIDE + n0 + 1] = v1;
            }
    }
    __syncthreads();

    // channel-quarter partial logits (vectorized): warp w -> pg=w&3, cg=w>>2
    const int pg = w & 3;
    const int cg = w >> 2;
    const int pos = pg * 32 + l;
    float lg[25];
#pragma unroll
    for (int n = 0; n < 25; n++) lg[n] = 0.f;
    {
        const float* xrow = xs + pos * XS_STRIDE + cg * 64;
        const float* wbse = w2s + (cg * 64) * 28;
#pragma unroll 4
        for (int k4 = 0; k4 < 16; k4++) {
            float4 xv4 = *(const float4*)(xrow + k4 * 4);
#pragma unroll
            for (int j = 0; j < 4; j++) {
                float xv = (j == 0) ? xv4.x : (j == 1) ? xv4.y : (j == 2) ? xv4.z : xv4.w;
                const float* wp = wbse + (k4 * 4 + j) * 28;
#pragma unroll
                for (int q = 0; q < 6; q++) {
                    float4 wv = *(const float4*)(wp + q * 4);
                    lg[q * 4 + 0] = fmaf(xv, wv.x, lg[q * 4 + 0]);
                    lg[q * 4 + 1] = fmaf(xv, wv.y, lg[q * 4 + 1]);
                    lg[q * 4 + 2] = fmaf(xv, wv.z, lg[q * 4 + 2]);
                    lg[q * 4 + 3] = fmaf(xv, wv.w, lg[q * 4 + 3]);
                }
                lg[24] = fmaf(xv, wp[24], lg[24]);
            }
        }
    }
    __syncthreads();                          // xs dead -> overlay red

    float* red = smf;                         // [4][128][26]
#pragma unroll
    for (int n = 0; n < 25; n++) red[(cg * 128 + pos) * 26 + n] = lg[n];
    __syncthreads();

    if (t < 128) {
        float v[25];
        float mx = -1e30f;
#pragma unroll
        for (int n = 0; n < 25; n++) {
            v[n] = red[t * 26 + n] + red[(128 + t) * 26 + n]
                 + red[(256 + t) * 26 + n] + red[(384 + t) * 26 + n] + b2s[n];
            mx = fmaxf(mx, v[n]);
        }
        float sum = 0.f;
#pragma unroll
        for (int n = 0; n < 25; n++) { v[n] = __expf(v[n] - mx); sum += v[n]; }
        float inv = 1.f / sum;
        int m = m0 + t;
        int b = m / 576;
        int pb = m - b * 576;
        float* kp = g_kmap + (size_t)b * 14400 + pb;
#pragma unroll
        for (int n = 0; n < 25; n++) kp[(size_t)n * 576] = v[n] * inv;
    }
}

// ---------------- 25-tap propagation: all channels staged, 1 barrier --------
#define CSPLIT 8
#define CPB    32

__global__ __launch_bounds__(192) void prop_kernel(const float* __restrict__ src,
                                                   float* __restrict__ out) {
    __shared__ float patch[CPB][336];     // 42KB

    const int t = threadIdx.x;
    const int blk = blockIdx.x;
    const int cs = blk & (CSPLIT - 1);
    const int brg = blk >> 3;
    const int b = brg / 3;
    const int rg = brg - b * 3;
    const int pos0 = rg * 192;
    const int y0 = rg * 8;
    const int c0 = cs * CPB;

    float pr[25];
    const float* kp = g_kmap + (size_t)b * 14400 + pos0 + t;
#pragma unroll
    for (int n = 0; n < 25; n++) pr[n] = kp[(size_t)n * 576];

    int off[2];
    bool val[2];
#pragma unroll
    for (int i = 0; i < 2; i++) {
        int e = t + i * 192;
        int ry = e / 28;
        int rx = e - ry * 28;
        int iy = y0 - 2 + ry;
        int ix = rx - 2;
        val[i] = (e < 336) && iy >= 0 && iy < 24 && ix >= 0 && ix < 24;
        off[i] = val[i] ? iy * 24 + ix : 0;
    }

    const float* sb = src + (size_t)b * 147456 + (size_t)c0 * 576;
    const int py = t / 24 + 2;
    const int px = t - (t / 24) * 24 + 2;
    const int pcenter = py * 28 + px;
    float* ob = out + (size_t)b * 147456 + (size_t)c0 * 576 + pos0 + t;

    // stage ALL 32 channels' patches
#pragma unroll 4
    for (int c = 0; c < CPB; ++c) {
#pragma unroll
        for (int i = 0; i < 2; i++) {
            int e = t + i * 192;
            if (e < 336) patch[c][e] = val[i] ? sb[(size_t)c * 576 + off[i]] : 0.f;
        }
    }
    __syncthreads();

    // pure compute: 32 channels, no further barriers
#pragma unroll 4
    for (int c = 0; c < CPB; ++c) {
        const float* pc = &patch[c][0];
        float sum = 0.f;
#pragma unroll
        for (int o = 0; o < 25; o++) {
            int ddy = o / 5 - 2;
            int ddx = o - (o / 5) * 5 - 2;
            sum = fmaf(pc[pcenter + ddy * 28 + ddx], pr[o], sum);
        }
        ob[(size_t)c * 576] = sum;
    }
}

// ---------------- launcher ----------------
extern "C" void kernel_launch(void* const* d_in, const int* in_sizes, int n_in,
                              void* d_out, int out_size) {
    const float* src = (const float*)d_in[0];
    const float* det = (const float*)d_in[1];
    const float* w1  = (const float*)d_in[2];
    const float* b1  = (const float*)d_in[3];
    const float* gam = (const float*)d_in[4];
    const float* bet = (const float*)d_in[5];
    const float* mu  = (const float*)d_in[6];
    const float* var = (const float*)d_in[7];
    const float* w2  = (const float*)d_in[8];
    const float* b2  = (const float*)d_in[9];
    float* out = (float*)d_out;

    cudaFuncSetAttribute(conv1_mma, cudaFuncAttributeMaxDynamicSharedMemorySize, CONV1_SMEM);

    wprep_kernel<<<(9 * 256 * KPRIME + 255) / 256, 256>>>(w1, b1, gam, bet, mu, var);
    xprep_kernel<<<128 * 26, 256>>>(src, det);

    conv1_mma<<<576, 512, CONV1_SMEM>>>(w2, b2);   // conv1+BN+ReLU+conv2+softmax

    prop_kernel<<<128 * 3 * CSPLIT, 192>>>(src, out);
}

// round 14
// speedup vs baseline: 1.1041x; 1.1041x over previous
#include <cuda_runtime.h>
#include <cuda_fp16.h>
#include <cstdint>
#include <math.h>

// ============================================================================
// conv1 via mma.sync fp16 (HMMA), pure fp16 inputs. K' = 4608 (9 taps * 512).
// Storage: padded 26x26 planes (zeros at borders) so tap shifts are linear.
// R14: R13 with xprep staging buffer moved to DYNAMIC smem (51200B > 48KB
// static limit). R11 conv1 + prop (best known); BN-fold merged into wprep;
// xprep uses half2 fully-coalesced stores, single pass over rows.
// ============================================================================

#define NPLANE   676
#define KPRIME   512               // per-tap k' (pure fp16)
#define N_CHUNKS 72                // 9 taps * 8 chunks of 64
#define STAGE_B  49152             // A 16KB + B 32KB
#define N_STAGE  4
#define CONV1_SMEM (N_STAGE * STAGE_B)   // 196608B; epilogue reuses this arena
#define XPREP_SMEM (512 * 25 * 4)        // 51200B dynamic

// epilogue smem layout (floats):
#define XS_STRIDE 292
#define W2S_OFF   37376
#define B2S_OFF   44544

// ---------------- static device scratch ----------------
__device__ __half g_xs[130 * NPLANE * KPRIME];   // padded NHWC fp16 (~90MB)
__device__ __half g_wb[9 * 256 * KPRIME];        // weights [tap][n][k]
__device__ float g_scale[256];
__device__ float g_shift[256];
__device__ float g_kmap[128 * 25 * 576];         // softmax maps

// ---------------- PTX helpers ----------------
__device__ __forceinline__ uint32_t smem_u32(const void* p) {
    uint32_t a;
    asm("{ .reg .u64 t; cvta.to.shared.u64 t, %1; cvt.u32.u64 %0, t; }" : "=r"(a) : "l"(p));
    return a;
}
#define CP_ASYNC16(dst, src) \
    asm volatile("cp.async.cg.shared.global [%0], [%1], 16;" :: "r"(dst), "l"(src) : "memory")
#define CP_COMMIT() asm volatile("cp.async.commit_group;" ::: "memory")
#define CP_WAIT(n)  asm volatile("cp.async.wait_group %0;" :: "n"(n) : "memory")

__device__ __forceinline__ void ldsm_x4(uint32_t* r, uint32_t addr) {
    asm volatile("ldmatrix.sync.aligned.m8n8.x4.shared.b16 {%0,%1,%2,%3}, [%4];"
                 : "=r"(r[0]), "=r"(r[1]), "=r"(r[2]), "=r"(r[3]) : "r"(addr));
}
__device__ __forceinline__ void mma_f16(float* c, const uint32_t* a, uint32_t b0, uint32_t b1) {
    asm volatile("mma.sync.aligned.m16n8k16.row.col.f32.f16.f16.f32 "
                 "{%0,%1,%2,%3}, {%4,%5,%6,%7}, {%8,%9}, {%0,%1,%2,%3};"
                 : "+f"(c[0]), "+f"(c[1]), "+f"(c[2]), "+f"(c[3])
                 : "r"(a[0]), "r"(a[1]), "r"(a[2]), "r"(a[3]), "r"(b0), "r"(b1));
}

// ---------------- prep: weights -> fp16 [tap][n][k]  (+ BN fold in block 0) --
__global__ void wprep_kernel(const float* __restrict__ w1,
                             const float* __restrict__ b1, const float* __restrict__ gam,
                             const float* __restrict__ bet, const float* __restrict__ mu,
                             const float* __restrict__ var) {
    int idx = blockIdx.x * 256 + threadIdx.x;
    if (blockIdx.x == 0) {
        int i = threadIdx.x;
        float inv = gam[i] * rsqrtf(var[i] + 1e-5f);
        g_scale[i] = inv;
        g_shift[i] = bet[i] + (b1[i] - mu[i]) * inv;
    }
    if (idx >= 9 * 256 * KPRIME) return;
    int kp = idx & 511;
    int n = (idx >> 9) & 255;
    int tap = idx >> 17;
    g_wb[idx] = __float2half(w1[((size_t)n * 512 + kp) * 9 + tap]);
}

// ---------------- prep: inputs -> padded NHWC fp16, half2 coalesced stores ---
__global__ __launch_bounds__(256) void xprep_kernel(const float* __restrict__ src,
                                                    const float* __restrict__ det) {
    extern __shared__ float s[];   // [512][25], dynamic (51200B)
    int blk = blockIdx.x;
    int p = blk / 26 + 1;          // planes 1..128 (guards never read)
    int yq = blk % 26;
    int t = threadIdx.x;
    __half* rowout = g_xs + (size_t)(p * NPLANE + yq * 26) * KPRIME;
    if (yq < 1 || yq > 24) {       // pad rows
        uint4 z = make_uint4(0, 0, 0, 0);
        uint4* o = (uint4*)rowout;
        for (int e = t; e < 26 * KPRIME / 8; e += 256) o[e] = z;
        return;
    }
    int b = p - 1, y = yq - 1;
    {   // zero x-pad columns (x''=0, 25)
        uint4 z = make_uint4(0, 0, 0, 0);
        uint4* o0 = (uint4*)rowout;
        uint4* o1 = (uint4*)(rowout + (size_t)25 * KPRIME);
        for (int e = t; e < KPRIME / 8; e += 256) { o0[e] = z; o1[e] = z; }
    }
    // stage all 512 channels (src then det)
    for (int e = t; e < 512 * 24; e += 256) {
        int ch = e / 24, x = e - ch * 24;
        const float* in = (ch < 256) ? src : det;
        s[ch * 25 + x] = in[((size_t)b * 256 + (ch & 255)) * 576 + y * 24 + x];
    }
    __syncthreads();
    // one half2 per thread per row: fully coalesced 1KB row stores
    for (int x = 0; x < 24; ++x) {
        __half2* o = (__half2*)(rowout + (size_t)(x + 1) * KPRIME);
        o[t] = __floats2half2_rn(s[(2 * t) * 25 + x], s[(2 * t + 1) * 25 + x]);
    }
}

// ---------------- conv1 + conv2 + softmax fused (R11 structure) ----------
__global__ __launch_bounds__(512) void conv1_mma(const float* __restrict__ w2,
                                                 const float* __restrict__ b2) {
    extern __shared__ __align__(1024) char smem_raw[];
    const uint32_t sbase = smem_u32(smem_raw);

    const int t = threadIdx.x;
    const int l = t & 31;
    const int w = t >> 5;                   // 0..15
    const int m0 = blockIdx.x * 128;

    const int arow = t >> 2;
    const int aq = t & 3;
    uint32_t sdstA[2];
#pragma unroll
    for (int g = 0; g < 2; g++) {
        int ch = aq * 2 + g;
        sdstA[g] = (uint32_t)arow * 128u + (uint32_t)((ch ^ (arow & 7)) * 16);
    }
    size_t abase;
    {
        const int mg = m0 + arow;
        const int b = mg / 576;
        const int pos = mg - b * 576;
        const int yy = pos / 24;
        const int xx = pos - yy * 24;
        abase = ((size_t)(b + 1) * NPLANE + (yy + 1) * 26 + (xx + 1)) * KPRIME
              + (size_t)aq * 16;
    }
    const int brow = t >> 1;
    const int bh = t & 1;
    uint32_t sdstB[4];
#pragma unroll
    for (int g = 0; g < 4; g++) {
        int ch = bh * 4 + g;
        sdstB[g] = 16384u + (uint32_t)brow * 128u + (uint32_t)((ch ^ (brow & 7)) * 16);
    }

    const int wm = (w >> 2) * 32;
    const int wn = (w & 3) * 64;
    const uint32_t rsw = (uint32_t)(l & 7);
    const uint32_t kHi = (uint32_t)(l >> 4);
    uint32_t aRow[2], bRow[4];
#pragma unroll
    for (int mi = 0; mi < 2; mi++) aRow[mi] = (uint32_t)(wm + mi * 16 + (l & 15)) * 128u;
#pragma unroll
    for (int gi = 0; gi < 4; gi++) bRow[gi] = 16384u + (uint32_t)(wn + gi * 16 + (l & 15)) * 128u;

    float acc[2][8][4];
#pragma unroll
    for (int mi = 0; mi < 2; mi++)
#pragma unroll
        for (int ni = 0; ni < 8; ni++)
#pragma unroll
            for (int r = 0; r < 4; r++) acc[mi][ni][r] = 0.f;

    auto issue = [&](int c) {
        const int tap = c >> 3;
        const int kc = (c & 7) * 64;
        const int ty = tap / 3, tx = tap - ty * 3;
        const int shift = (ty - 1) * 26 + (tx - 1);
        const uint32_t St = sbase + (uint32_t)(c & (N_STAGE - 1)) * STAGE_B;
        const __half* asrc = g_xs + abase + (ptrdiff_t)shift * KPRIME + kc;
        const __half* bsrc = g_wb + ((size_t)(tap * 256 + brow)) * KPRIME + kc + bh * 32;
#pragma unroll
        for (int g = 0; g < 2; g++) CP_ASYNC16(St + sdstA[g], asrc + g * 8);
#pragma unroll
        for (int g = 0; g < 4; g++) CP_ASYNC16(St + sdstB[g], bsrc + g * 8);
    };

    uint32_t af[2][2][4], bf[2][4][4];
    auto load_frag = [&](uint32_t St, int ks, int buf) {
        const uint32_t off = (((uint32_t)(ks * 2) + kHi) ^ rsw) << 4;
#pragma unroll
        for (int mi = 0; mi < 2; mi++) ldsm_x4(af[buf][mi], St + aRow[mi] + off);
#pragma unroll
        for (int gi = 0; gi < 4; gi++) ldsm_x4(bf[buf][gi], St + bRow[gi] + off);
    };
    auto mma_frag = [&](int buf) {
#pragma unroll
        for (int mi = 0; mi < 2; mi++)
#pragma unroll
            for (int gi = 0; gi < 4; gi++) {
                mma_f16(acc[mi][gi * 2 + 0], af[buf][mi], bf[buf][gi][0], bf[buf][gi][2]);
                mma_f16(acc[mi][gi * 2 + 1], af[buf][mi], bf[buf][gi][1], bf[buf][gi][3]);
            }
    };

    issue(0); CP_COMMIT();
    issue(1); CP_COMMIT();
    issue(2); CP_COMMIT();
    for (int c = 0; c < N_CHUNKS; ++c) {
        if (c < N_CHUNKS - 2) { CP_WAIT(1); } else { CP_WAIT(0); }
        __syncthreads();
        if (c + 3 < N_CHUNKS) { issue(c + 3); CP_COMMIT(); }
        const uint32_t St  = sbase + (uint32_t)(c & (N_STAGE - 1)) * STAGE_B;
        const uint32_t Stn = sbase + (uint32_t)((c + 1) & (N_STAGE - 1)) * STAGE_B;
        if (c == 0) load_frag(St, 0, 0);
#pragma unroll
        for (int ks = 0; ks < 4; ks++) {
            if (ks < 3) load_frag(St, ks + 1, (ks + 1) & 1);
            else if (c + 1 < N_CHUNKS) load_frag(Stn, 0, 0);
            mma_frag(ks & 1);
        }
    }

    // ====== fused epilogue: BN+ReLU -> conv2 -> softmax ======
    __syncthreads();
    float* smf = (float*)smem_raw;
    float* xs  = smf;
    float* w2s = smf + W2S_OFF;
    float* b2s = smf + B2S_OFF;

    for (int e = t; e < 25 * 256; e += 512) {
        int n = e >> 8, ch = e & 255;
        w2s[ch * 28 + n] = w2[n * 256 + ch];
    }
    if (t < 25) b2s[t] = b2[t];

#pragma unroll
    for (int ni = 0; ni < 8; ni++) {
        int n0 = wn + (ni >> 1) * 16 + (ni & 1) * 8 + (l & 3) * 2;
        float sc0 = g_scale[n0], sh0 = g_shift[n0];
        float sc1 = g_scale[n0 + 1], sh1 = g_shift[n0 + 1];
#pragma unroll
        for (int mi = 0; mi < 2; mi++)
#pragma unroll
            for (int h = 0; h < 2; h++) {
                int ml = wm + mi * 16 + (l >> 2) + h * 8;
                float v0 = fmaxf(fmaf(acc[mi][ni][h * 2 + 0], sc0, sh0), 0.f);
                float v1 = fmaxf(fmaf(acc[mi][ni][h * 2 + 1], sc1, sh1), 0.f);
                xs[ml * XS_STRIDE + n0] = v0;
                xs[ml * XS_STRIDE + n0 + 1] = v1;
            }
    }
    __syncthreads();

    const int pg = w & 3;
    const int cg = w >> 2;
    const int pos = pg * 32 + l;
    float lg[25];
#pragma unroll
    for (int n = 0; n < 25; n++) lg[n] = 0.f;
    {
        const float* xrow = xs + pos * XS_STRIDE + cg * 64;
        const float* wbse = w2s + (cg * 64) * 28;
#pragma unroll 4
        for (int k4 = 0; k4 < 16; k4++) {
            float4 xv4 = *(const float4*)(xrow + k4 * 4);
#pragma unroll
            for (int j = 0; j < 4; j++) {
                float xv = (j == 0) ? xv4.x : (j == 1) ? xv4.y : (j == 2) ? xv4.z : xv4.w;
                const float* wp = wbse + (k4 * 4 + j) * 28;
#pragma unroll
                for (int q = 0; q < 6; q++) {
                    float4 wv = *(const float4*)(wp + q * 4);
                    lg[q * 4 + 0] = fmaf(xv, wv.x, lg[q * 4 + 0]);
                    lg[q * 4 + 1] = fmaf(xv, wv.y, lg[q * 4 + 1]);
                    lg[q * 4 + 2] = fmaf(xv, wv.z, lg[q * 4 + 2]);
                    lg[q * 4 + 3] = fmaf(xv, wv.w, lg[q * 4 + 3]);
                }
                lg[24] = fmaf(xv, wp[24], lg[24]);
            }
        }
    }
    __syncthreads();

    float* red = smf;                         // [4][128][26]
#pragma unroll
    for (int n = 0; n < 25; n++) red[(cg * 128 + pos) * 26 + n] = lg[n];
    __syncthreads();

    if (t < 128) {
        float v[25];
        float mx = -1e30f;
#pragma unroll
        for (int n = 0; n < 25; n++) {
            v[n] = red[t * 26 + n] + red[(128 + t) * 26 + n]
                 + red[(256 + t) * 26 + n] + red[(384 + t) * 26 + n] + b2s[n];
            mx = fmaxf(mx, v[n]);
        }
        float sum = 0.f;
#pragma unroll
        for (int n = 0; n < 25; n++) { v[n] = __expf(v[n] - mx); sum += v[n]; }
        float inv = 1.f / sum;
        int m = m0 + t;
        int b = m / 576;
        int pb = m - b * 576;
        float* kp = g_kmap + (size_t)b * 14400 + pb;
#pragma unroll
        for (int n = 0; n < 25; n++) kp[(size_t)n * 576] = v[n] * inv;
    }
}

// ---------------- 25-tap propagation (R11: 2-channel rolling buffer) --------
#define CSPLIT 8
#define CPB    32

__global__ __launch_bounds__(192) void prop_kernel(const float* __restrict__ src,
                                                   float* __restrict__ out) {
    __shared__ float patch[2][336];

    const int t = threadIdx.x;
    const int blk = blockIdx.x;
    const int cs = blk & (CSPLIT - 1);
    const int brg = blk >> 3;
    const int b = brg / 3;
    const int rg = brg - b * 3;
    const int pos0 = rg * 192;
    const int y0 = rg * 8;
    const int c0 = cs * CPB;

    float pr[25];
    const float* kp = g_kmap + (size_t)b * 14400 + pos0 + t;
#pragma unroll
    for (int n = 0; n < 25; n++) pr[n] = kp[(size_t)n * 576];

    int off[2];
    bool val[2];
#pragma unroll
    for (int i = 0; i < 2; i++) {
        int e = t + i * 192;
        int ry = e / 28;
        int rx = e - ry * 28;
        int iy = y0 - 2 + ry;
        int ix = rx - 2;
        val[i] = (e < 336) && iy >= 0 && iy < 24 && ix >= 0 && ix < 24;
        off[i] = val[i] ? iy * 24 + ix : 0;
    }

    const float* sb = src + (size_t)b * 147456 + (size_t)c0 * 576;
    const int py = t / 24 + 2;
    const int px = t - (t / 24) * 24 + 2;
    const int pcenter = py * 28 + px;
    float* ob = out + (size_t)b * 147456 + (size_t)c0 * 576 + pos0 + t;

#pragma unroll
    for (int i = 0; i < 2; i++) {
        int e = t + i * 192;
        if (e < 336) patch[0][e] = val[i] ? sb[off[i]] : 0.f;
    }
    __syncthreads();

    for (int c = 0; c < CPB; ++c) {
        float nv[2];
        if (c + 1 < CPB) {
#pragma unroll
            for (int i = 0; i < 2; i++)
                nv[i] = val[i] ? sb[(size_t)(c + 1) * 576 + off[i]] : 0.f;
        }
        const float* pc = &patch[c & 1][0];
        float sum = 0.f;
#pragma unroll
        for (int o = 0; o < 25; o++) {
            int ddy = o / 5 - 2;
            int ddx = o - (o / 5) * 5 - 2;
            sum = fmaf(pc[pcenter + ddy * 28 + ddx], pr[o], sum);
        }
        ob[(size_t)c * 576] = sum;

        if (c + 1 < CPB) {
#pragma unroll
            for (int i = 0; i < 2; i++) {
                int e = t + i * 192;
                if (e < 336) patch[(c + 1) & 1][e] = nv[i];
            }
        }
        __syncthreads();
    }
}

// ---------------- launcher ----------------
extern "C" void kernel_launch(void* const* d_in, const int* in_sizes, int n_in,
                              void* d_out, int out_size) {
    const float* src = (const float*)d_in[0];
    const float* det = (const float*)d_in[1];
    const float* w1  = (const float*)d_in[2];
    const float* b1  = (const float*)d_in[3];
    const float* gam = (const float*)d_in[4];
    const float* bet = (const float*)d_in[5];
    const float* mu  = (const float*)d_in[6];
    const float* var = (const float*)d_in[7];
    const float* w2  = (const float*)d_in[8];
    const float* b2  = (const float*)d_in[9];
    float* out = (float*)d_out;

    cudaFuncSetAttribute(conv1_mma, cudaFuncAttributeMaxDynamicSharedMemorySize, CONV1_SMEM);
    cudaFuncSetAttribute(xprep_kernel, cudaFuncAttributeMaxDynamicSharedMemorySize, XPREP_SMEM);

    wprep_kernel<<<(9 * 256 * KPRIME + 255) / 256, 256>>>(w1, b1, gam, bet, mu, var);
    xprep_kernel<<<128 * 26, 256, XPREP_SMEM>>>(src, det);

    conv1_mma<<<576, 512, CONV1_SMEM>>>(w2, b2);   // conv1+BN+ReLU+conv2+softmax

    prop_kernel<<<128 * 3 * CSPLIT, 192>>>(src, out);
}

// round 15
// speedup vs baseline: 1.1322x; 1.0255x over previous
#include <cuda_runtime.h>
#include <cuda_fp16.h>
#include <cstdint>
#include <math.h>

// ============================================================================
// conv1 via mma.sync fp16 (HMMA), pure fp16 inputs. K' = 4608 (9 taps * 512).
// Storage: padded 26x26 planes (zeros at borders) so tap shifts are linear.
// R15: prop register-blocked 2 output rows/thread (30 LDS per 2 outputs vs 50)
// full-image 28x28 patch, 288 thr/block. conv1/xprep/wprep = R14 exact.
// ============================================================================

#define NPLANE   676
#define KPRIME   512               // per-tap k' (pure fp16)
#define N_CHUNKS 72                // 9 taps * 8 chunks of 64
#define STAGE_B  49152             // A 16KB + B 32KB
#define N_STAGE  4
#define CONV1_SMEM (N_STAGE * STAGE_B)   // 196608B; epilogue reuses this arena
#define XPREP_SMEM (512 * 25 * 4)        // 51200B dynamic

// epilogue smem layout (floats):
#define XS_STRIDE 292
#define W2S_OFF   37376
#define B2S_OFF   44544

// ---------------- static device scratch ----------------
__device__ __half g_xs[130 * NPLANE * KPRIME];   // padded NHWC fp16 (~90MB)
__device__ __half g_wb[9 * 256 * KPRIME];        // weights [tap][n][k]
__device__ float g_scale[256];
__device__ float g_shift[256];
__device__ float g_kmap[128 * 25 * 576];         // softmax maps

// ---------------- PTX helpers ----------------
__device__ __forceinline__ uint32_t smem_u32(const void* p) {
    uint32_t a;
    asm("{ .reg .u64 t; cvta.to.shared.u64 t, %1; cvt.u32.u64 %0, t; }" : "=r"(a) : "l"(p));
    return a;
}
#define CP_ASYNC16(dst, src) \
    asm volatile("cp.async.cg.shared.global [%0], [%1], 16;" :: "r"(dst), "l"(src) : "memory")
#define CP_COMMIT() asm volatile("cp.async.commit_group;" ::: "memory")
#define CP_WAIT(n)  asm volatile("cp.async.wait_group %0;" :: "n"(n) : "memory")

__device__ __forceinline__ void ldsm_x4(uint32_t* r, uint32_t addr) {
    asm volatile("ldmatrix.sync.aligned.m8n8.x4.shared.b16 {%0,%1,%2,%3}, [%4];"
                 : "=r"(r[0]), "=r"(r[1]), "=r"(r[2]), "=r"(r[3]) : "r"(addr));
}
__device__ __forceinline__ void mma_f16(float* c, const uint32_t* a, uint32_t b0, uint32_t b1) {
    asm volatile("mma.sync.aligned.m16n8k16.row.col.f32.f16.f16.f32 "
                 "{%0,%1,%2,%3}, {%4,%5,%6,%7}, {%8,%9}, {%0,%1,%2,%3};"
                 : "+f"(c[0]), "+f"(c[1]), "+f"(c[2]), "+f"(c[3])
                 : "r"(a[0]), "r"(a[1]), "r"(a[2]), "r"(a[3]), "r"(b0), "r"(b1));
}

// ---------------- prep: weights -> fp16 [tap][n][k]  (+ BN fold in block 0) --
__global__ void wprep_kernel(const float* __restrict__ w1,
                             const float* __restrict__ b1, const float* __restrict__ gam,
                             const float* __restrict__ bet, const float* __restrict__ mu,
                             const float* __restrict__ var) {
    int idx = blockIdx.x * 256 + threadIdx.x;
    if (blockIdx.x == 0) {
        int i = threadIdx.x;
        float inv = gam[i] * rsqrtf(var[i] + 1e-5f);
        g_scale[i] = inv;
        g_shift[i] = bet[i] + (b1[i] - mu[i]) * inv;
    }
    if (idx >= 9 * 256 * KPRIME) return;
    int kp = idx & 511;
    int n = (idx >> 9) & 255;
    int tap = idx >> 17;
    g_wb[idx] = __float2half(w1[((size_t)n * 512 + kp) * 9 + tap]);
}

// ---------------- prep: inputs -> padded NHWC fp16, half2 coalesced stores ---
__global__ __launch_bounds__(256) void xprep_kernel(const float* __restrict__ src,
                                                    const float* __restrict__ det) {
    extern __shared__ float s[];   // [512][25], dynamic (51200B)
    int blk = blockIdx.x;
    int p = blk / 26 + 1;          // planes 1..128 (guards never read)
    int yq = blk % 26;
    int t = threadIdx.x;
    __half* rowout = g_xs + (size_t)(p * NPLANE + yq * 26) * KPRIME;
    if (yq < 1 || yq > 24) {       // pad rows
        uint4 z = make_uint4(0, 0, 0, 0);
        uint4* o = (uint4*)rowout;
        for (int e = t; e < 26 * KPRIME / 8; e += 256) o[e] = z;
        return;
    }
    int b = p - 1, y = yq - 1;
    {   // zero x-pad columns (x''=0, 25)
        uint4 z = make_uint4(0, 0, 0, 0);
        uint4* o0 = (uint4*)rowout;
        uint4* o1 = (uint4*)(rowout + (size_t)25 * KPRIME);
        for (int e = t; e < KPRIME / 8; e += 256) { o0[e] = z; o1[e] = z; }
    }
    for (int e = t; e < 512 * 24; e += 256) {
        int ch = e / 24, x = e - ch * 24;
        const float* in = (ch < 256) ? src : det;
        s[ch * 25 + x] = in[((size_t)b * 256 + (ch & 255)) * 576 + y * 24 + x];
    }
    __syncthreads();
    for (int x = 0; x < 24; ++x) {
        __half2* o = (__half2*)(rowout + (size_t)(x + 1) * KPRIME);
        o[t] = __floats2half2_rn(s[(2 * t) * 25 + x], s[(2 * t + 1) * 25 + x]);
    }
}

// ---------------- conv1 + conv2 + softmax fused (R11 structure) ----------
__global__ __launch_bounds__(512) void conv1_mma(const float* __restrict__ w2,
                                                 const float* __restrict__ b2) {
    extern __shared__ __align__(1024) char smem_raw[];
    const uint32_t sbase = smem_u32(smem_raw);

    const int t = threadIdx.x;
    const int l = t & 31;
    const int w = t >> 5;                   // 0..15
    const int m0 = blockIdx.x * 128;

    const int arow = t >> 2;
    const int aq = t & 3;
    uint32_t sdstA[2];
#pragma unroll
    for (int g = 0; g < 2; g++) {
        int ch = aq * 2 + g;
        sdstA[g] = (uint32_t)arow * 128u + (uint32_t)((ch ^ (arow & 7)) * 16);
    }
    size_t abase;
    {
        const int mg = m0 + arow;
        const int b = mg / 576;
        const int pos = mg - b * 576;
        const int yy = pos / 24;
        const int xx = pos - yy * 24;
        abase = ((size_t)(b + 1) * NPLANE + (yy + 1) * 26 + (xx + 1)) * KPRIME
              + (size_t)aq * 16;
    }
    const int brow = t >> 1;
    const int bh = t & 1;
    uint32_t sdstB[4];
#pragma unroll
    for (int g = 0; g < 4; g++) {
        int ch = bh * 4 + g;
        sdstB[g] = 16384u + (uint32_t)brow * 128u + (uint32_t)((ch ^ (brow & 7)) * 16);
    }

    const int wm = (w >> 2) * 32;
    const int wn = (w & 3) * 64;
    const uint32_t rsw = (uint32_t)(l & 7);
    const uint32_t kHi = (uint32_t)(l >> 4);
    uint32_t aRow[2], bRow[4];
#pragma unroll
    for (int mi = 0; mi < 2; mi++) aRow[mi] = (uint32_t)(wm + mi * 16 + (l & 15)) * 128u;
#pragma unroll
    for (int gi = 0; gi < 4; gi++) bRow[gi] = 16384u + (uint32_t)(wn + gi * 16 + (l & 15)) * 128u;

    float acc[2][8][4];
#pragma unroll
    for (int mi = 0; mi < 2; mi++)
#pragma unroll
        for (int ni = 0; ni < 8; ni++)
#pragma unroll
            for (int r = 0; r < 4; r++) acc[mi][ni][r] = 0.f;

    auto issue = [&](int c) {
        const int tap = c >> 3;
        const int kc = (c & 7) * 64;
        const int ty = tap / 3, tx = tap - ty * 3;
        const int shift = (ty - 1) * 26 + (tx - 1);
        const uint32_t St = sbase + (uint32_t)(c & (N_STAGE - 1)) * STAGE_B;
        const __half* asrc = g_xs + abase + (ptrdiff_t)shift * KPRIME + kc;
        const __half* bsrc = g_wb + ((size_t)(tap * 256 + brow)) * KPRIME + kc + bh * 32;
#pragma unroll
        for (int g = 0; g < 2; g++) CP_ASYNC16(St + sdstA[g], asrc + g * 8);
#pragma unroll
        for (int g = 0; g < 4; g++) CP_ASYNC16(St + sdstB[g], bsrc + g * 8);
    };

    uint32_t af[2][2][4], bf[2][4][4];
    auto load_frag = [&](uint32_t St, int ks, int buf) {
        const uint32_t off = (((uint32_t)(ks * 2) + kHi) ^ rsw) << 4;
#pragma unroll
        for (int mi = 0; mi < 2; mi++) ldsm_x4(af[buf][mi], St + aRow[mi] + off);
#pragma unroll
        for (int gi = 0; gi < 4; gi++) ldsm_x4(bf[buf][gi], St + bRow[gi] + off);
    };
    auto mma_frag = [&](int buf) {
#pragma unroll
        for (int mi = 0; mi < 2; mi++)
#pragma unroll
            for (int gi = 0; gi < 4; gi++) {
                mma_f16(acc[mi][gi * 2 + 0], af[buf][mi], bf[buf][gi][0], bf[buf][gi][2]);
                mma_f16(acc[mi][gi * 2 + 1], af[buf][mi], bf[buf][gi][1], bf[buf][gi][3]);
            }
    };

    issue(0); CP_COMMIT();
    issue(1); CP_COMMIT();
    issue(2); CP_COMMIT();
    for (int c = 0; c < N_CHUNKS; ++c) {
        if (c < N_CHUNKS - 2) { CP_WAIT(1); } else { CP_WAIT(0); }
        __syncthreads();
        if (c + 3 < N_CHUNKS) { issue(c + 3); CP_COMMIT(); }
        const uint32_t St  = sbase + (uint32_t)(c & (N_STAGE - 1)) * STAGE_B;
        const uint32_t Stn = sbase + (uint32_t)((c + 1) & (N_STAGE - 1)) * STAGE_B;
        if (c == 0) load_frag(St, 0, 0);
#pragma unroll
        for (int ks = 0; ks < 4; ks++) {
            if (ks < 3) load_frag(St, ks + 1, (ks + 1) & 1);
            else if (c + 1 < N_CHUNKS) load_frag(Stn, 0, 0);
            mma_frag(ks & 1);
        }
    }

    // ====== fused epilogue: BN+ReLU -> conv2 -> softmax ======
    __syncthreads();
    float* smf = (float*)smem_raw;
    float* xs  = smf;
    float* w2s = smf + W2S_OFF;
    float* b2s = smf + B2S_OFF;

    for (int e = t; e < 25 * 256; e += 512) {
        int n = e >> 8, ch = e & 255;
        w2s[ch * 28 + n] = w2[n * 256 + ch];
    }
    if (t < 25) b2s[t] = b2[t];

#pragma unroll
    for (int ni = 0; ni < 8; ni++) {
        int n0 = wn + (ni >> 1) * 16 + (ni & 1) * 8 + (l & 3) * 2;
        float sc0 = g_scale[n0], sh0 = g_shift[n0];
        float sc1 = g_scale[n0 + 1], sh1 = g_shift[n0 + 1];
#pragma unroll
        for (int mi = 0; mi < 2; mi++)
#pragma unroll
            for (int h = 0; h < 2; h++) {
                int ml = wm + mi * 16 + (l >> 2) + h * 8;
                float v0 = fmaxf(fmaf(acc[mi][ni][h * 2 + 0], sc0, sh0), 0.f);
                float v1 = fmaxf(fmaf(acc[mi][ni][h * 2 + 1], sc1, sh1), 0.f);
                xs[ml * XS_STRIDE + n0] = v0;
                xs[ml * XS_STRIDE + n0 + 1] = v1;
            }
    }
    __syncthreads();

    const int pg = w & 3;
    const int cg = w >> 2;
    const int pos = pg * 32 + l;
    float lg[25];
#pragma unroll
    for (int n = 0; n < 25; n++) lg[n] = 0.f;
    {
        const float* xrow = xs + pos * XS_STRIDE + cg * 64;
        const float* wbse = w2s + (cg * 64) * 28;
#pragma unroll 4
        for (int k4 = 0; k4 < 16; k4++) {
            float4 xv4 = *(const float4*)(xrow + k4 * 4);
#pragma unroll
            for (int j = 0; j < 4; j++) {
                float xv = (j == 0) ? xv4.x : (j == 1) ? xv4.y : (j == 2) ? xv4.z : xv4.w;
                const float* wp = wbse + (k4 * 4 + j) * 28;
#pragma unroll
                for (int q = 0; q < 6; q++) {
                    float4 wv = *(const float4*)(wp + q * 4);
                    lg[q * 4 + 0] = fmaf(xv, wv.x, lg[q * 4 + 0]);
                    lg[q * 4 + 1] = fmaf(xv, wv.y, lg[q * 4 + 1]);
                    lg[q * 4 + 2] = fmaf(xv, wv.z, lg[q * 4 + 2]);
                    lg[q * 4 + 3] = fmaf(xv, wv.w, lg[q * 4 + 3]);
                }
                lg[24] = fmaf(xv, wp[24], lg[24]);
            }
        }
    }
    __syncthreads();

    float* red = smf;                         // [4][128][26]
#pragma unroll
    for (int n = 0; n < 25; n++) red[(cg * 128 + pos) * 26 + n] = lg[n];
    __syncthreads();

    if (t < 128) {
        float v[25];
        float mx = -1e30f;
#pragma unroll
        for (int n = 0; n < 25; n++) {
            v[n] = red[t * 26 + n] + red[(128 + t) * 26 + n]
                 + red[(256 + t) * 26 + n] + red[(384 + t) * 26 + n] + b2s[n];
            mx = fmaxf(mx, v[n]);
        }
        float sum = 0.f;
#pragma unroll
        for (int n = 0; n < 25; n++) { v[n] = __expf(v[n] - mx); sum += v[n]; }
        float inv = 1.f / sum;
        int m = m0 + t;
        int b = m / 576;
        int pb = m - b * 576;
        float* kp = g_kmap + (size_t)b * 14400 + pb;
#pragma unroll
        for (int n = 0; n < 25; n++) kp[(size_t)n * 576] = v[n] * inv;
    }
}

// ---------------- 25-tap propagation: 2 output rows per thread --------------
// block = (batch, 32-ch slice); 288 thr = 12 thread-rows x 24 cols; each
// thread computes outputs (2ty, x) and (2ty+1, x). 28x28 padded patch per
// channel, double-buffered, 1 barrier/channel; 30 LDS per 2 outputs.
#define CSPLIT 8
#define CPB    32

__global__ __launch_bounds__(288) void prop_kernel(const float* __restrict__ src,
                                                   float* __restrict__ out) {
    __shared__ float patch[2][784];   // 28x28

    const int t = threadIdx.x;
    const int blk = blockIdx.x;
    const int cs = blk & (CSPLIT - 1);
    const int b = blk >> 3;
    const int c0 = cs * CPB;

    const int ty = t / 24;            // 0..11
    const int x  = t - ty * 24;
    const int y0 = ty * 2;            // output rows y0, y0+1
    const int pos0 = y0 * 24 + x;

    float pr0[25], pr1[25];
    const float* kp = g_kmap + (size_t)b * 14400;
#pragma unroll
    for (int n = 0; n < 25; n++) {
        pr0[n] = kp[(size_t)n * 576 + pos0];
        pr1[n] = kp[(size_t)n * 576 + pos0 + 24];
    }

    // staging: 784 elements / 288 threads -> up to 3 each
    int off[3];
    bool val[3];
#pragma unroll
    for (int i = 0; i < 3; i++) {
        int e = t + i * 288;
        int ry = e / 28;
        int rx = e - ry * 28;
        int iy = ry - 2;
        int ix = rx - 2;
        val[i] = (e < 784) && iy >= 0 && iy < 24 && ix >= 0 && ix < 24;
        off[i] = val[i] ? iy * 24 + ix : 0;
    }

    const float* sb = src + (size_t)b * 147456 + (size_t)c0 * 576;
    float* ob = out + (size_t)b * 147456 + (size_t)c0 * 576 + pos0;

    // prime channel 0
#pragma unroll
    for (int i = 0; i < 3; i++) {
        int e = t + i * 288;
        if (e < 784) patch[0][e] = val[i] ? sb[off[i]] : 0.f;
    }
    __syncthreads();

    for (int c = 0; c < CPB; ++c) {
        float nv[3];
        if (c + 1 < CPB) {
#pragma unroll
            for (int i = 0; i < 3; i++)
                nv[i] = val[i] ? sb[(size_t)(c + 1) * 576 + off[i]] : 0.f;
        }
        const float* pc = &patch[c & 1][0];
        float s0 = 0.f, s1 = 0.f;
        // rows r=0..5 cover input rows y0-2 .. y0+3 (patch rows y0 .. y0+5)
#pragma unroll
        for (int r = 0; r < 6; r++) {
            const float* pp = pc + (y0 + r) * 28 + x;
            float v0 = pp[0], v1 = pp[1], v2 = pp[2], v3 = pp[3], v4 = pp[4];
            if (r < 5) {
                s0 = fmaf(v0, pr0[r * 5 + 0], s0);
                s0 = fmaf(v1, pr0[r * 5 + 1], s0);
                s0 = fmaf(v2, pr0[r * 5 + 2], s0);
                s0 = fmaf(v3, pr0[r * 5 + 3], s0);
                s0 = fmaf(v4, pr0[r * 5 + 4], s0);
            }
            if (r >= 1) {
                s1 = fmaf(v0, pr1[(r - 1) * 5 + 0], s1);
                s1 = fmaf(v1, pr1[(r - 1) * 5 + 1], s1);
                s1 = fmaf(v2, pr1[(r - 1) * 5 + 2], s1);
                s1 = fmaf(v3, pr1[(r - 1) * 5 + 3], s1);
                s1 = fmaf(v4, pr1[(r - 1) * 5 + 4], s1);
            }
        }
        ob[(size_t)c * 576] = s0;
        ob[(size_t)c * 576 + 24] = s1;

        if (c + 1 < CPB) {
#pragma unroll
            for (int i = 0; i < 3; i++) {
                int e = t + i * 288;
                if (e < 784) patch[(c + 1) & 1][e] = nv[i];
            }
        }
        __syncthreads();
    }
}

// ---------------- launcher ----------------
extern "C" void kernel_launch(void* const* d_in, const int* in_sizes, int n_in,
                              void* d_out, int out_size) {
    const float* src = (const float*)d_in[0];
    const float* det = (const float*)d_in[1];
    const float* w1  = (const float*)d_in[2];
    const float* b1  = (const float*)d_in[3];
    const float* gam = (const float*)d_in[4];
    const float* bet = (const float*)d_in[5];
    const float* mu  = (const float*)d_in[6];
    const float* var = (const float*)d_in[7];
    const float* w2  = (const float*)d_in[8];
    const float* b2  = (const float*)d_in[9];
    float* out = (float*)d_out;

    cudaFuncSetAttribute(conv1_mma, cudaFuncAttributeMaxDynamicSharedMemorySize, CONV1_SMEM);
    cudaFuncSetAttribute(xprep_kernel, cudaFuncAttributeMaxDynamicSharedMemorySize, XPREP_SMEM);

    wprep_kernel<<<(9 * 256 * KPRIME + 255) / 256, 256>>>(w1, b1, gam, bet, mu, var);
    xprep_kernel<<<128 * 26, 256, XPREP_SMEM>>>(src, det);

    conv1_mma<<<576, 512, CONV1_SMEM>>>(w2, b2);   // conv1+BN+ReLU+conv2+softmax

    prop_kernel<<<128 * CSPLIT, 288>>>(src, out);
}

// round 16
// speedup vs baseline: 1.1378x; 1.0049x over previous
#include <cuda_runtime.h>
#include <cuda_fp16.h>
#include <cstdint>
#include <math.h>

// ============================================================================
// conv1 via mma.sync fp16 (HMMA), pure fp16 inputs. K' = 4608 (9 taps * 512).
// Storage: padded 26x26 planes (zeros at borders) so tap shifts are linear.
// R16: prop CSPLIT 16 (2048 blocks, 2x latency cover); wprep+xprep fused into
// one launch (disjoint outputs). conv1 = R11/R14 exact (calibrated plateau).
// ============================================================================

#define NPLANE   676
#define KPRIME   512               // per-tap k' (pure fp16)
#define N_CHUNKS 72                // 9 taps * 8 chunks of 64
#define STAGE_B  49152             // A 16KB + B 32KB
#define N_STAGE  4
#define CONV1_SMEM (N_STAGE * STAGE_B)   // 196608B; epilogue reuses this arena
#define PREP_SMEM (512 * 25 * 4)         // 51200B dynamic (xprep staging)
#define WPREP_BLOCKS 4608                // 9*256*512 / 256
#define XPREP_BLOCKS (128 * 26)

// epilogue smem layout (floats):
#define XS_STRIDE 292
#define W2S_OFF   37376
#define B2S_OFF   44544

// ---------------- static device scratch ----------------
__device__ __half g_xs[130 * NPLANE * KPRIME];   // padded NHWC fp16 (~90MB)
__device__ __half g_wb[9 * 256 * KPRIME];        // weights [tap][n][k]
__device__ float g_scale[256];
__device__ float g_shift[256];
__device__ float g_kmap[128 * 25 * 576];         // softmax maps

// ---------------- PTX helpers ----------------
__device__ __forceinline__ uint32_t smem_u32(const void* p) {
    uint32_t a;
    asm("{ .reg .u64 t; cvta.to.shared.u64 t, %1; cvt.u32.u64 %0, t; }" : "=r"(a) : "l"(p));
    return a;
}
#define CP_ASYNC16(dst, src) \
    asm volatile("cp.async.cg.shared.global [%0], [%1], 16;" :: "r"(dst), "l"(src) : "memory")
#define CP_COMMIT() asm volatile("cp.async.commit_group;" ::: "memory")
#define CP_WAIT(n)  asm volatile("cp.async.wait_group %0;" :: "n"(n) : "memory")

__device__ __forceinline__ void ldsm_x4(uint32_t* r, uint32_t addr) {
    asm volatile("ldmatrix.sync.aligned.m8n8.x4.shared.b16 {%0,%1,%2,%3}, [%4];"
                 : "=r"(r[0]), "=r"(r[1]), "=r"(r[2]), "=r"(r[3]) : "r"(addr));
}
__device__ __forceinline__ void mma_f16(float* c, const uint32_t* a, uint32_t b0, uint32_t b1) {
    asm volatile("mma.sync.aligned.m16n8k16.row.col.f32.f16.f16.f32 "
                 "{%0,%1,%2,%3}, {%4,%5,%6,%7}, {%8,%9}, {%0,%1,%2,%3};"
                 : "+f"(c[0]), "+f"(c[1]), "+f"(c[2]), "+f"(c[3])
                 : "r"(a[0]), "r"(a[1]), "r"(a[2]), "r"(a[3]), "r"(b0), "r"(b1));
}

// ---------------- fused prep: weights + BN fold + padded-input build --------
__global__ __launch_bounds__(256) void prep_kernel(
    const float* __restrict__ w1,
    const float* __restrict__ b1, const float* __restrict__ gam,
    const float* __restrict__ bet, const float* __restrict__ mu,
    const float* __restrict__ var,
    const float* __restrict__ src, const float* __restrict__ det) {
    extern __shared__ float s[];   // xprep staging [512][25]
    int t = threadIdx.x;

    if (blockIdx.x < WPREP_BLOCKS) {
        // ---- weight transform ----
        int idx = blockIdx.x * 256 + t;
        if (blockIdx.x == 0) {
            float inv = gam[t] * rsqrtf(var[t] + 1e-5f);
            g_scale[t] = inv;
            g_shift[t] = bet[t] + (b1[t] - mu[t]) * inv;
        }
        int kp = idx & 511;
        int n = (idx >> 9) & 255;
        int tap = idx >> 17;
        g_wb[idx] = __float2half(w1[((size_t)n * 512 + kp) * 9 + tap]);
        return;
    }

    // ---- padded-input build ----
    int blk = blockIdx.x - WPREP_BLOCKS;
    int p = blk / 26 + 1;          // planes 1..128 (guards never read)
    int yq = blk % 26;
    __half* rowout = g_xs + (size_t)(p * NPLANE + yq * 26) * KPRIME;
    if (yq < 1 || yq > 24) {       // pad rows
        uint4 z = make_uint4(0, 0, 0, 0);
        uint4* o = (uint4*)rowout;
        for (int e = t; e < 26 * KPRIME / 8; e += 256) o[e] = z;
        return;
    }
    int b = p - 1, y = yq - 1;
    {   // zero x-pad columns (x''=0, 25)
        uint4 z = make_uint4(0, 0, 0, 0);
        uint4* o0 = (uint4*)rowout;
        uint4* o1 = (uint4*)(rowout + (size_t)25 * KPRIME);
        for (int e = t; e < KPRIME / 8; e += 256) { o0[e] = z; o1[e] = z; }
    }
    for (int e = t; e < 512 * 24; e += 256) {
        int ch = e / 24, x = e - ch * 24;
        const float* in = (ch < 256) ? src : det;
        s[ch * 25 + x] = in[((size_t)b * 256 + (ch & 255)) * 576 + y * 24 + x];
    }
    __syncthreads();
    for (int x = 0; x < 24; ++x) {
        __half2* o = (__half2*)(rowout + (size_t)(x + 1) * KPRIME);
        o[t] = __floats2half2_rn(s[(2 * t) * 25 + x], s[(2 * t + 1) * 25 + x]);
    }
}

// ---------------- conv1 + conv2 + softmax fused (R11 structure) ----------
__global__ __launch_bounds__(512) void conv1_mma(const float* __restrict__ w2,
                                                 const float* __restrict__ b2) {
    extern __shared__ __align__(1024) char smem_raw[];
    const uint32_t sbase = smem_u32(smem_raw);

    const int t = threadIdx.x;
    const int l = t & 31;
    const int w = t >> 5;                   // 0..15
    const int m0 = blockIdx.x * 128;

    const int arow = t >> 2;
    const int aq = t & 3;
    uint32_t sdstA[2];
#pragma unroll
    for (int g = 0; g < 2; g++) {
        int ch = aq * 2 + g;
        sdstA[g] = (uint32_t)arow * 128u + (uint32_t)((ch ^ (arow & 7)) * 16);
    }
    size_t abase;
    {
        const int mg = m0 + arow;
        const int b = mg / 576;
        const int pos = mg - b * 576;
        const int yy = pos / 24;
        const int xx = pos - yy * 24;
        abase = ((size_t)(b + 1) * NPLANE + (yy + 1) * 26 + (xx + 1)) * KPRIME
              + (size_t)aq * 16;
    }
    const int brow = t >> 1;
    const int bh = t & 1;
    uint32_t sdstB[4];
#pragma unroll
    for (int g = 0; g < 4; g++) {
        int ch = bh * 4 + g;
        sdstB[g] = 16384u + (uint32_t)brow * 128u + (uint32_t)((ch ^ (brow & 7)) * 16);
    }

    const int wm = (w >> 2) * 32;
    const int wn = (w & 3) * 64;
    const uint32_t rsw = (uint32_t)(l & 7);
    const uint32_t kHi = (uint32_t)(l >> 4);
    uint32_t aRow[2], bRow[4];
#pragma unroll
    for (int mi = 0; mi < 2; mi++) aRow[mi] = (uint32_t)(wm + mi * 16 + (l & 15)) * 128u;
#pragma unroll
    for (int gi = 0; gi < 4; gi++) bRow[gi] = 16384u + (uint32_t)(wn + gi * 16 + (l & 15)) * 128u;

    float acc[2][8][4];
#pragma unroll
    for (int mi = 0; mi < 2; mi++)
#pragma unroll
        for (int ni = 0; ni < 8; ni++)
#pragma unroll
            for (int r = 0; r < 4; r++) acc[mi][ni][r] = 0.f;

    auto issue = [&](int c) {
        const int tap = c >> 3;
        const int kc = (c & 7) * 64;
        const int ty = tap / 3, tx = tap - ty * 3;
        const int shift = (ty - 1) * 26 + (tx - 1);
        const uint32_t St = sbase + (uint32_t)(c & (N_STAGE - 1)) * STAGE_B;
        const __half* asrc = g_xs + abase + (ptrdiff_t)shift * KPRIME + kc;
        const __half* bsrc = g_wb + ((size_t)(tap * 256 + brow)) * KPRIME + kc + bh * 32;
#pragma unroll
        for (int g = 0; g < 2; g++) CP_ASYNC16(St + sdstA[g], asrc + g * 8);
#pragma unroll
        for (int g = 0; g < 4; g++) CP_ASYNC16(St + sdstB[g], bsrc + g * 8);
    };

    uint32_t af[2][2][4], bf[2][4][4];
    auto load_frag = [&](uint32_t St, int ks, int buf) {
        const uint32_t off = (((uint32_t)(ks * 2) + kHi) ^ rsw) << 4;
#pragma unroll
        for (int mi = 0; mi < 2; mi++) ldsm_x4(af[buf][mi], St + aRow[mi] + off);
#pragma unroll
        for (int gi = 0; gi < 4; gi++) ldsm_x4(bf[buf][gi], St + bRow[gi] + off);
    };
    auto mma_frag = [&](int buf) {
#pragma unroll
        for (int mi = 0; mi < 2; mi++)
#pragma unroll
            for (int gi = 0; gi < 4; gi++) {
                mma_f16(acc[mi][gi * 2 + 0], af[buf][mi], bf[buf][gi][0], bf[buf][gi][2]);
                mma_f16(acc[mi][gi * 2 + 1], af[buf][mi], bf[buf][gi][1], bf[buf][gi][3]);
            }
    };

    issue(0); CP_COMMIT();
    issue(1); CP_COMMIT();
    issue(2); CP_COMMIT();
    for (int c = 0; c < N_CHUNKS; ++c) {
        if (c < N_CHUNKS - 2) { CP_WAIT(1); } else { CP_WAIT(0); }
        __syncthreads();
        if (c + 3 < N_CHUNKS) { issue(c + 3); CP_COMMIT(); }
        const uint32_t St  = sbase + (uint32_t)(c & (N_STAGE - 1)) * STAGE_B;
        const uint32_t Stn = sbase + (uint32_t)((c + 1) & (N_STAGE - 1)) * STAGE_B;
        if (c == 0) load_frag(St, 0, 0);
#pragma unroll
        for (int ks = 0; ks < 4; ks++) {
            if (ks < 3) load_frag(St, ks + 1, (ks + 1) & 1);
            else if (c + 1 < N_CHUNKS) load_frag(Stn, 0, 0);
            mma_frag(ks & 1);
        }
    }

    // ====== fused epilogue: BN+ReLU -> conv2 -> softmax ======
    __syncthreads();
    float* smf = (float*)smem_raw;
    float* xs  = smf;
    float* w2s = smf + W2S_OFF;
    float* b2s = smf + B2S_OFF;

    for (int e = t; e < 25 * 256; e += 512) {
        int n = e >> 8, ch = e & 255;
        w2s[ch * 28 + n] = w2[n * 256 + ch];
    }
    if (t < 25) b2s[t] = b2[t];

#pragma unroll
    for (int ni = 0; ni < 8; ni++) {
        int n0 = wn + (ni >> 1) * 16 + (ni & 1) * 8 + (l & 3) * 2;
        float sc0 = g_scale[n0], sh0 = g_shift[n0];
        float sc1 = g_scale[n0 + 1], sh1 = g_shift[n0 + 1];
#pragma unroll
        for (int mi = 0; mi < 2; mi++)
#pragma unroll
            for (int h = 0; h < 2; h++) {
                int ml = wm + mi * 16 + (l >> 2) + h * 8;
                float v0 = fmaxf(fmaf(acc[mi][ni][h * 2 + 0], sc0, sh0), 0.f);
                float v1 = fmaxf(fmaf(acc[mi][ni][h * 2 + 1], sc1, sh1), 0.f);
                xs[ml * XS_STRIDE + n0] = v0;
                xs[ml * XS_STRIDE + n0 + 1] = v1;
            }
    }
    __syncthreads();

    const int pg = w & 3;
    const int cg = w >> 2;
    const int pos = pg * 32 + l;
    float lg[25];
#pragma unroll
    for (int n = 0; n < 25; n++) lg[n] = 0.f;
    {
        const float* xrow = xs + pos * XS_STRIDE + cg * 64;
        const float* wbse = w2s + (cg * 64) * 28;
#pragma unroll 4
        for (int k4 = 0; k4 < 16; k4++) {
            float4 xv4 = *(const float4*)(xrow + k4 * 4);
#pragma unroll
            for (int j = 0; j < 4; j++) {
                float xv = (j == 0) ? xv4.x : (j == 1) ? xv4.y : (j == 2) ? xv4.z : xv4.w;
                const float* wp = wbse + (k4 * 4 + j) * 28;
#pragma unroll
                for (int q = 0; q < 6; q++) {
                    float4 wv = *(const float4*)(wp + q * 4);
                    lg[q * 4 + 0] = fmaf(xv, wv.x, lg[q * 4 + 0]);
                    lg[q * 4 + 1] = fmaf(xv, wv.y, lg[q * 4 + 1]);
                    lg[q * 4 + 2] = fmaf(xv, wv.z, lg[q * 4 + 2]);
                    lg[q * 4 + 3] = fmaf(xv, wv.w, lg[q * 4 + 3]);
                }
                lg[24] = fmaf(xv, wp[24], lg[24]);
            }
        }
    }
    __syncthreads();

    float* red = smf;                         // [4][128][26]
#pragma unroll
    for (int n = 0; n < 25; n++) red[(cg * 128 + pos) * 26 + n] = lg[n];
    __syncthreads();

    if (t < 128) {
        float v[25];
        float mx = -1e30f;
#pragma unroll
        for (int n = 0; n < 25; n++) {
            v[n] = red[t * 26 + n] + red[(128 + t) * 26 + n]
                 + red[(256 + t) * 26 + n] + red[(384 + t) * 26 + n] + b2s[n];
            mx = fmaxf(mx, v[n]);
        }
        float sum = 0.f;
#pragma unroll
        for (int n = 0; n < 25; n++) { v[n] = __expf(v[n] - mx); sum += v[n]; }
        float inv = 1.f / sum;
        int m = m0 + t;
        int b = m / 576;
        int pb = m - b * 576;
        float* kp = g_kmap + (size_t)b * 14400 + pb;
#pragma unroll
        for (int n = 0; n < 25; n++) kp[(size_t)n * 576] = v[n] * inv;
    }
}

// ---------------- 25-tap propagation: 2 output rows per thread --------------
// block = (batch, 16-ch slice); 288 thr = 12 thread-rows x 24 cols.
#define CSPLIT 16
#define CPB    16

__global__ __launch_bounds__(288) void prop_kernel(const float* __restrict__ src,
                                                   float* __restrict__ out) {
    __shared__ float patch[2][784];   // 28x28

    const int t = threadIdx.x;
    const int blk = blockIdx.x;
    const int cs = blk & (CSPLIT - 1);
    const int b = blk >> 4;
    const int c0 = cs * CPB;

    const int ty = t / 24;            // 0..11
    const int x  = t - ty * 24;
    const int y0 = ty * 2;            // output rows y0, y0+1
    const int pos0 = y0 * 24 + x;

    float pr0[25], pr1[25];
    const float* kp = g_kmap + (size_t)b * 14400;
#pragma unroll
    for (int n = 0; n < 25; n++) {
        pr0[n] = kp[(size_t)n * 576 + pos0];
        pr1[n] = kp[(size_t)n * 576 + pos0 + 24];
    }

    int off[3];
    bool val[3];
#pragma unroll
    for (int i = 0; i < 3; i++) {
        int e = t + i * 288;
        int ry = e / 28;
        int rx = e - ry * 28;
        int iy = ry - 2;
        int ix = rx - 2;
        val[i] = (e < 784) && iy >= 0 && iy < 24 && ix >= 0 && ix < 24;
        off[i] = val[i] ? iy * 24 + ix : 0;
    }

    const float* sb = src + (size_t)b * 147456 + (size_t)c0 * 576;
    float* ob = out + (size_t)b * 147456 + (size_t)c0 * 576 + pos0;

#pragma unroll
    for (int i = 0; i < 3; i++) {
        int e = t + i * 288;
        if (e < 784) patch[0][e] = val[i] ? sb[off[i]] : 0.f;
    }
    __syncthreads();

    for (int c = 0; c < CPB; ++c) {
        float nv[3];
        if (c + 1 < CPB) {
#pragma unroll
            for (int i = 0; i < 3; i++)
                nv[i] = val[i] ? sb[(size_t)(c + 1) * 576 + off[i]] : 0.f;
        }
        const float* pc = &patch[c & 1][0];
        float s0 = 0.f, s1 = 0.f;
#pragma unroll
        for (int r = 0; r < 6; r++) {
            const float* pp = pc + (y0 + r) * 28 + x;
            float v0 = pp[0], v1 = pp[1], v2 = pp[2], v3 = pp[3], v4 = pp[4];
            if (r < 5) {
                s0 = fmaf(v0, pr0[r * 5 + 0], s0);
                s0 = fmaf(v1, pr0[r * 5 + 1], s0);
                s0 = fmaf(v2, pr0[r * 5 + 2], s0);
                s0 = fmaf(v3, pr0[r * 5 + 3], s0);
                s0 = fmaf(v4, pr0[r * 5 + 4], s0);
            }
            if (r >= 1) {
                s1 = fmaf(v0, pr1[(r - 1) * 5 + 0], s1);
                s1 = fmaf(v1, pr1[(r - 1) * 5 + 1], s1);
                s1 = fmaf(v2, pr1[(r - 1) * 5 + 2], s1);
                s1 = fmaf(v3, pr1[(r - 1) * 5 + 3], s1);
                s1 = fmaf(v4, pr1[(r - 1) * 5 + 4], s1);
            }
        }
        ob[(size_t)c * 576] = s0;
        ob[(size_t)c * 576 + 24] = s1;

        if (c + 1 < CPB) {
#pragma unroll
            for (int i = 0; i < 3; i++) {
                int e = t + i * 288;
                if (e < 784) patch[(c + 1) & 1][e] = nv[i];
            }
        }
        __syncthreads();
    }
}

// ---------------- launcher ----------------
extern "C" void kernel_launch(void* const* d_in, const int* in_sizes, int n_in,
                              void* d_out, int out_size) {
    const float* src = (const float*)d_in[0];
    const float* det = (const float*)d_in[1];
    const float* w1  = (const float*)d_in[2];
    const float* b1  = (const float*)d_in[3];
    const float* gam = (const float*)d_in[4];
    const float* bet = (const float*)d_in[5];
    const float* mu  = (const float*)d_in[6];
    const float* var = (const float*)d_in[7];
    const float* w2  = (const float*)d_in[8];
    const float* b2  = (const float*)d_in[9];
    float* out = (float*)d_out;

    cudaFuncSetAttribute(conv1_mma, cudaFuncAttributeMaxDynamicSharedMemorySize, CONV1_SMEM);
    cudaFuncSetAttribute(prep_kernel, cudaFuncAttributeMaxDynamicSharedMemorySize, PREP_SMEM);

    prep_kernel<<<WPREP_BLOCKS + XPREP_BLOCKS, 256, PREP_SMEM>>>(
        w1, b1, gam, bet, mu, var, src, det);

    conv1_mma<<<576, 512, CONV1_SMEM>>>(w2, b2);   // conv1+BN+ReLU+conv2+softmax

    prop_kernel<<<128 * CSPLIT, 288>>>(src, out);
}

// round 17
// speedup vs baseline: 1.1380x; 1.0002x over previous
#include <cuda_runtime.h>
#include <cuda_fp16.h>
#include <cstdint>
#include <math.h>

// ============================================================================
// conv1 via mma.sync fp16 (HMMA), pure fp16 inputs. K' = 4608 (9 taps * 512).
// Storage: padded 26x26 planes (zeros at borders) so tap shifts are linear.
// R17: wprep rebuilt fully coalesced (1 block per n: contiguous w1-row read ->
// smem -> half2 coalesced writes). All else = R16 exact.
// ============================================================================

#define NPLANE   676
#define KPRIME   512               // per-tap k' (pure fp16)
#define N_CHUNKS 72                // 9 taps * 8 chunks of 64
#define STAGE_B  49152             // A 16KB + B 32KB
#define N_STAGE  4
#define CONV1_SMEM (N_STAGE * STAGE_B)   // 196608B; epilogue reuses this arena
#define PREP_SMEM (512 * 25 * 4)         // 51200B dynamic (covers 4608*4 wprep too)
#define WPREP_BLOCKS 256                 // one block per output channel n
#define XPREP_BLOCKS (128 * 26)

// epilogue smem layout (floats):
#define XS_STRIDE 292
#define W2S_OFF   37376
#define B2S_OFF   44544

// ---------------- static device scratch ----------------
__device__ __half g_xs[130 * NPLANE * KPRIME];   // padded NHWC fp16 (~90MB)
__device__ __half g_wb[9 * 256 * KPRIME];        // weights [tap][n][k]
__device__ float g_scale[256];
__device__ float g_shift[256];
__device__ float g_kmap[128 * 25 * 576];         // softmax maps

// ---------------- PTX helpers ----------------
__device__ __forceinline__ uint32_t smem_u32(const void* p) {
    uint32_t a;
    asm("{ .reg .u64 t; cvta.to.shared.u64 t, %1; cvt.u32.u64 %0, t; }" : "=r"(a) : "l"(p));
    return a;
}
#define CP_ASYNC16(dst, src) \
    asm volatile("cp.async.cg.shared.global [%0], [%1], 16;" :: "r"(dst), "l"(src) : "memory")
#define CP_COMMIT() asm volatile("cp.async.commit_group;" ::: "memory")
#define CP_WAIT(n)  asm volatile("cp.async.wait_group %0;" :: "n"(n) : "memory")

__device__ __forceinline__ void ldsm_x4(uint32_t* r, uint32_t addr) {
    asm volatile("ldmatrix.sync.aligned.m8n8.x4.shared.b16 {%0,%1,%2,%3}, [%4];"
                 : "=r"(r[0]), "=r"(r[1]), "=r"(r[2]), "=r"(r[3]) : "r"(addr));
}
__device__ __forceinline__ void mma_f16(float* c, const uint32_t* a, uint32_t b0, uint32_t b1) {
    asm volatile("mma.sync.aligned.m16n8k16.row.col.f32.f16.f16.f32 "
                 "{%0,%1,%2,%3}, {%4,%5,%6,%7}, {%8,%9}, {%0,%1,%2,%3};"
                 : "+f"(c[0]), "+f"(c[1]), "+f"(c[2]), "+f"(c[3])
                 : "r"(a[0]), "r"(a[1]), "r"(a[2]), "r"(a[3]), "r"(b0), "r"(b1));
}

// ---------------- fused prep: weights (coalesced) + BN fold + input build ---
__global__ __launch_bounds__(256) void prep_kernel(
    const float* __restrict__ w1,
    const float* __restrict__ b1, const float* __restrict__ gam,
    const float* __restrict__ bet, const float* __restrict__ mu,
    const float* __restrict__ var,
    const float* __restrict__ src, const float* __restrict__ det) {
    extern __shared__ float s[];   // staging: wprep 4608f / xprep [512][25]
    int t = threadIdx.x;

    if (blockIdx.x < WPREP_BLOCKS) {
        // ---- weight transform: block = output channel n ----
        int n = blockIdx.x;
        if (n == 0) {
            float inv = gam[t] * rsqrtf(var[t] + 1e-5f);
            g_scale[t] = inv;
            g_shift[t] = bet[t] + (b1[t] - mu[t]) * inv;
        }
        const float* wrow = w1 + (size_t)n * 4608;       // [c][tap] contiguous
        for (int e = t; e < 4608; e += 256) s[e] = wrow[e];
        __syncthreads();
#pragma unroll
        for (int tap = 0; tap < 9; tap++) {
            __half2* o = (__half2*)(g_wb + (size_t)tap * 131072 + (size_t)n * 512);
            o[t] = __floats2half2_rn(s[(2 * t) * 9 + tap], s[(2 * t + 1) * 9 + tap]);
        }
        return;
    }

    // ---- padded-input build ----
    int blk = blockIdx.x - WPREP_BLOCKS;
    int p = blk / 26 + 1;          // planes 1..128 (guards never read)
    int yq = blk % 26;
    __half* rowout = g_xs + (size_t)(p * NPLANE + yq * 26) * KPRIME;
    if (yq < 1 || yq > 24) {       // pad rows
        uint4 z = make_uint4(0, 0, 0, 0);
        uint4* o = (uint4*)rowout;
        for (int e = t; e < 26 * KPRIME / 8; e += 256) o[e] = z;
        return;
    }
    int b = p - 1, y = yq - 1;
    {   // zero x-pad columns (x''=0, 25)
        uint4 z = make_uint4(0, 0, 0, 0);
        uint4* o0 = (uint4*)rowout;
        uint4* o1 = (uint4*)(rowout + (size_t)25 * KPRIME);
        for (int e = t; e < KPRIME / 8; e += 256) { o0[e] = z; o1[e] = z; }
    }
    for (int e = t; e < 512 * 24; e += 256) {
        int ch = e / 24, x = e - ch * 24;
        const float* in = (ch < 256) ? src : det;
        s[ch * 25 + x] = in[((size_t)b * 256 + (ch & 255)) * 576 + y * 24 + x];
    }
    __syncthreads();
    for (int x = 0; x < 24; ++x) {
        __half2* o = (__half2*)(rowout + (size_t)(x + 1) * KPRIME);
        o[t] = __floats2half2_rn(s[(2 * t) * 25 + x], s[(2 * t + 1) * 25 + x]);
    }
}

// ---------------- conv1 + conv2 + softmax fused (R11 structure) ----------
__global__ __launch_bounds__(512) void conv1_mma(const float* __restrict__ w2,
                                                 const float* __restrict__ b2) {
    extern __shared__ __align__(1024) char smem_raw[];
    const uint32_t sbase = smem_u32(smem_raw);

    const int t = threadIdx.x;
    const int l = t & 31;
    const int w = t >> 5;                   // 0..15
    const int m0 = blockIdx.x * 128;

    const int arow = t >> 2;
    const int aq = t & 3;
    uint32_t sdstA[2];
#pragma unroll
    for (int g = 0; g < 2; g++) {
        int ch = aq * 2 + g;
        sdstA[g] = (uint32_t)arow * 128u + (uint32_t)((ch ^ (arow & 7)) * 16);
    }
    size_t abase;
    {
        const int mg = m0 + arow;
        const int b = mg / 576;
        const int pos = mg - b * 576;
        const int yy = pos / 24;
        const int xx = pos - yy * 24;
        abase = ((size_t)(b + 1) * NPLANE + (yy + 1) * 26 + (xx + 1)) * KPRIME
              + (size_t)aq * 16;
    }
    const int brow = t >> 1;
    const int bh = t & 1;
    uint32_t sdstB[4];
#pragma unroll
    for (int g = 0; g < 4; g++) {
        int ch = bh * 4 + g;
        sdstB[g] = 16384u + (uint32_t)brow * 128u + (uint32_t)((ch ^ (brow & 7)) * 16);
    }

    const int wm = (w >> 2) * 32;
    const int wn = (w & 3) * 64;
    const uint32_t rsw = (uint32_t)(l & 7);
    const uint32_t kHi = (uint32_t)(l >> 4);
    uint32_t aRow[2], bRow[4];
#pragma unroll
    for (int mi = 0; mi < 2; mi++) aRow[mi] = (uint32_t)(wm + mi * 16 + (l & 15)) * 128u;
#pragma unroll
    for (int gi = 0; gi < 4; gi++) bRow[gi] = 16384u + (uint32_t)(wn + gi * 16 + (l & 15)) * 128u;

    float acc[2][8][4];
#pragma unroll
    for (int mi = 0; mi < 2; mi++)
#pragma unroll
        for (int ni = 0; ni < 8; ni++)
#pragma unroll
            for (int r = 0; r < 4; r++) acc[mi][ni][r] = 0.f;

    auto issue = [&](int c) {
        const int tap = c >> 3;
        const int kc = (c & 7) * 64;
        const int ty = tap / 3, tx = tap - ty * 3;
        const int shift = (ty - 1) * 26 + (tx - 1);
        const uint32_t St = sbase + (uint32_t)(c & (N_STAGE - 1)) * STAGE_B;
        const __half* asrc = g_xs + abase + (ptrdiff_t)shift * KPRIME + kc;
        const __half* bsrc = g_wb + ((size_t)(tap * 256 + brow)) * KPRIME + kc + bh * 32;
#pragma unroll
        for (int g = 0; g < 2; g++) CP_ASYNC16(St + sdstA[g], asrc + g * 8);
#pragma unroll
        for (int g = 0; g < 4; g++) CP_ASYNC16(St + sdstB[g], bsrc + g * 8);
    };

    uint32_t af[2][2][4], bf[2][4][4];
    auto load_frag = [&](uint32_t St, int ks, int buf) {
        const uint32_t off = (((uint32_t)(ks * 2) + kHi) ^ rsw) << 4;
#pragma unroll
        for (int mi = 0; mi < 2; mi++) ldsm_x4(af[buf][mi], St + aRow[mi] + off);
#pragma unroll
        for (int gi = 0; gi < 4; gi++) ldsm_x4(bf[buf][gi], St + bRow[gi] + off);
    };
    auto mma_frag = [&](int buf) {
#pragma unroll
        for (int mi = 0; mi < 2; mi++)
#pragma unroll
            for (int gi = 0; gi < 4; gi++) {
                mma_f16(acc[mi][gi * 2 + 0], af[buf][mi], bf[buf][gi][0], bf[buf][gi][2]);
                mma_f16(acc[mi][gi * 2 + 1], af[buf][mi], bf[buf][gi][1], bf[buf][gi][3]);
            }
    };

    issue(0); CP_COMMIT();
    issue(1); CP_COMMIT();
    issue(2); CP_COMMIT();
    for (int c = 0; c < N_CHUNKS; ++c) {
        if (c < N_CHUNKS - 2) { CP_WAIT(1); } else { CP_WAIT(0); }
        __syncthreads();
        if (c + 3 < N_CHUNKS) { issue(c + 3); CP_COMMIT(); }
        const uint32_t St  = sbase + (uint32_t)(c & (N_STAGE - 1)) * STAGE_B;
        const uint32_t Stn = sbase + (uint32_t)((c + 1) & (N_STAGE - 1)) * STAGE_B;
        if (c == 0) load_frag(St, 0, 0);
#pragma unroll
        for (int ks = 0; ks < 4; ks++) {
            if (ks < 3) load_frag(St, ks + 1, (ks + 1) & 1);
            else if (c + 1 < N_CHUNKS) load_frag(Stn, 0, 0);
            mma_frag(ks & 1);
        }
    }

    // ====== fused epilogue: BN+ReLU -> conv2 -> softmax ======
    __syncthreads();
    float* smf = (float*)smem_raw;
    float* xs  = smf;
    float* w2s = smf + W2S_OFF;
    float* b2s = smf + B2S_OFF;

    for (int e = t; e < 25 * 256; e += 512) {
        int n = e >> 8, ch = e & 255;
        w2s[ch * 28 + n] = w2[n * 256 + ch];
    }
    if (t < 25) b2s[t] = b2[t];

#pragma unroll
    for (int ni = 0; ni < 8; ni++) {
        int n0 = wn + (ni >> 1) * 16 + (ni & 1) * 8 + (l & 3) * 2;
        float sc0 = g_scale[n0], sh0 = g_shift[n0];
        float sc1 = g_scale[n0 + 1], sh1 = g_shift[n0 + 1];
#pragma unroll
        for (int mi = 0; mi < 2; mi++)
#pragma unroll
            for (int h = 0; h < 2; h++) {
                int ml = wm + mi * 16 + (l >> 2) + h * 8;
                float v0 = fmaxf(fmaf(acc[mi][ni][h * 2 + 0], sc0, sh0), 0.f);
                float v1 = fmaxf(fmaf(acc[mi][ni][h * 2 + 1], sc1, sh1), 0.f);
                xs[ml * XS_STRIDE + n0] = v0;
                xs[ml * XS_STRIDE + n0 + 1] = v1;
            }
    }
    __syncthreads();

    const int pg = w & 3;
    const int cg = w >> 2;
    const int pos = pg * 32 + l;
    float lg[25];
#pragma unroll
    for (int n = 0; n < 25; n++) lg[n] = 0.f;
    {
        const float* xrow = xs + pos * XS_STRIDE + cg * 64;
        const float* wbse = w2s + (cg * 64) * 28;
#pragma unroll 4
        for (int k4 = 0; k4 < 16; k4++) {
            float4 xv4 = *(const float4*)(xrow + k4 * 4);
#pragma unroll
            for (int j = 0; j < 4; j++) {
                float xv = (j == 0) ? xv4.x : (j == 1) ? xv4.y : (j == 2) ? xv4.z : xv4.w;
                const float* wp = wbse + (k4 * 4 + j) * 28;
#pragma unroll
                for (int q = 0; q < 6; q++) {
                    float4 wv = *(const float4*)(wp + q * 4);
                    lg[q * 4 + 0] = fmaf(xv, wv.x, lg[q * 4 + 0]);
                    lg[q * 4 + 1] = fmaf(xv, wv.y, lg[q * 4 + 1]);
                    lg[q * 4 + 2] = fmaf(xv, wv.z, lg[q * 4 + 2]);
                    lg[q * 4 + 3] = fmaf(xv, wv.w, lg[q * 4 + 3]);
                }
                lg[24] = fmaf(xv, wp[24], lg[24]);
            }
        }
    }
    __syncthreads();

    float* red = smf;                         // [4][128][26]
#pragma unroll
    for (int n = 0; n < 25; n++) red[(cg * 128 + pos) * 26 + n] = lg[n];
    __syncthreads();

    if (t < 128) {
        float v[25];
        float mx = -1e30f;
#pragma unroll
        for (int n = 0; n < 25; n++) {
            v[n] = red[t * 26 + n] + red[(128 + t) * 26 + n]
                 + red[(256 + t) * 26 + n] + red[(384 + t) * 26 + n] + b2s[n];
            mx = fmaxf(mx, v[n]);
        }
        float sum = 0.f;
#pragma unroll
        for (int n = 0; n < 25; n++) { v[n] = __expf(v[n] - mx); sum += v[n]; }
        float inv = 1.f / sum;
        int m = m0 + t;
        int b = m / 576;
        int pb = m - b * 576;
        float* kp = g_kmap + (size_t)b * 14400 + pb;
#pragma unroll
        for (int n = 0; n < 25; n++) kp[(size_t)n * 576] = v[n] * inv;
    }
}

// ---------------- 25-tap propagation: 2 output rows per thread --------------
#define CSPLIT 16
#define CPB    16

__global__ __launch_bounds__(288) void prop_kernel(const float* __restrict__ src,
                                                   float* __restrict__ out) {
    __shared__ float patch[2][784];   // 28x28

    const int t = threadIdx.x;
    const int blk = blockIdx.x;
    const int cs = blk & (CSPLIT - 1);
    const int b = blk >> 4;
    const int c0 = cs * CPB;

    const int ty = t / 24;            // 0..11
    const int x  = t - ty * 24;
    const int y0 = ty * 2;            // output rows y0, y0+1
    const int pos0 = y0 * 24 + x;

    float pr0[25], pr1[25];
    const float* kp = g_kmap + (size_t)b * 14400;
#pragma unroll
    for (int n = 0; n < 25; n++) {
        pr0[n] = kp[(size_t)n * 576 + pos0];
        pr1[n] = kp[(size_t)n * 576 + pos0 + 24];
    }

    int off[3];
    bool val[3];
#pragma unroll
    for (int i = 0; i < 3; i++) {
        int e = t + i * 288;
        int ry = e / 28;
        int rx = e - ry * 28;
        int iy = ry - 2;
        int ix = rx - 2;
        val[i] = (e < 784) && iy >= 0 && iy < 24 && ix >= 0 && ix < 24;
        off[i] = val[i] ? iy * 24 + ix : 0;
    }

    const float* sb = src + (size_t)b * 147456 + (size_t)c0 * 576;
    float* ob = out + (size_t)b * 147456 + (size_t)c0 * 576 + pos0;

#pragma unroll
    for (int i = 0; i < 3; i++) {
        int e = t + i * 288;
        if (e < 784) patch[0][e] = val[i] ? sb[off[i]] : 0.f;
    }
    __syncthreads();

    for (int c = 0; c < CPB; ++c) {
        float nv[3];
        if (c + 1 < CPB) {
#pragma unroll
            for (int i = 0; i < 3; i++)
                nv[i] = val[i] ? sb[(size_t)(c + 1) * 576 + off[i]] : 0.f;
        }
        const float* pc = &patch[c & 1][0];
        float s0 = 0.f, s1 = 0.f;
#pragma unroll
        for (int r = 0; r < 6; r++) {
            const float* pp = pc + (y0 + r) * 28 + x;
            float v0 = pp[0], v1 = pp[1], v2 = pp[2], v3 = pp[3], v4 = pp[4];
            if (r < 5) {
                s0 = fmaf(v0, pr0[r * 5 + 0], s0);
                s0 = fmaf(v1, pr0[r * 5 + 1], s0);
                s0 = fmaf(v2, pr0[r * 5 + 2], s0);
                s0 = fmaf(v3, pr0[r * 5 + 3], s0);
                s0 = fmaf(v4, pr0[r * 5 + 4], s0);
            }
            if (r >= 1) {
                s1 = fmaf(v0, pr1[(r - 1) * 5 + 0], s1);
                s1 = fmaf(v1, pr1[(r - 1) * 5 + 1], s1);
                s1 = fmaf(v2, pr1[(r - 1) * 5 + 2], s1);
                s1 = fmaf(v3, pr1[(r - 1) * 5 + 3], s1);
                s1 = fmaf(v4, pr1[(r - 1) * 5 + 4], s1);
            }
        }
        ob[(size_t)c * 576] = s0;
        ob[(size_t)c * 576 + 24] = s1;

        if (c + 1 < CPB) {
#pragma unroll
            for (int i = 0; i < 3; i++) {
                int e = t + i * 288;
                if (e < 784) patch[(c + 1) & 1][e] = nv[i];
            }
        }
        __syncthreads();
    }
}

// ---------------- launcher ----------------
extern "C" void kernel_launch(void* const* d_in, const int* in_sizes, int n_in,
                              void* d_out, int out_size) {
    const float* src = (const float*)d_in[0];
    const float* det = (const float*)d_in[1];
    const float* w1  = (const float*)d_in[2];
    const float* b1  = (const float*)d_in[3];
    const float* gam = (const float*)d_in[4];
    const float* bet = (const float*)d_in[5];
    const float* mu  = (const float*)d_in[6];
    const float* var = (const float*)d_in[7];
    const float* w2  = (const float*)d_in[8];
    const float* b2  = (const float*)d_in[9];
    float* out = (float*)d_out;

    cudaFuncSetAttribute(conv1_mma, cudaFuncAttributeMaxDynamicSharedMemorySize, CONV1_SMEM);
    cudaFuncSetAttribute(prep_kernel, cudaFuncAttributeMaxDynamicSharedMemorySize, PREP_SMEM);

    prep_kernel<<<WPREP_BLOCKS + XPREP_BLOCKS, 256, PREP_SMEM>>>(
        w1, b1, gam, bet, mu, var, src, det);

    conv1_mma<<<576, 512, CONV1_SMEM>>>(w2, b2);   // conv1+BN+ReLU+conv2+softmax

    prop_kernel<<<128 * CSPLIT, 288>>>(src, out);
}